// round 10
// baseline (speedup 1.0000x reference)
#include <cuda_runtime.h>
#include <stdint.h>

#define MAXN 100000
#define MAXE 1600000
#define IN_DIM 128
#define HID 64
#define LAT 32

// Scratch: device globals, referenced ONLY from device code.
__device__ __align__(16) float g_dinv[MAXN];
__device__ __align__(16) float g_norm[MAXE];       // per-edge normalized weight
__device__ __align__(16) float g_B0[MAXN * HID];   // XW1, later H
__device__ __align__(16) float g_B1[MAXN * HID];   // ACC1, later HWcat
__device__ __align__(16) float g_B2[MAXN * HID];   // ACC2 (fused mu|lv pre-bias)

// ---------------- degree ----------------
__global__ void k_init_deg(int n) {
    int i = blockIdx.x * blockDim.x + threadIdx.x;
    if (i < n) g_dinv[i] = 1.0f;  // self-loop weight
}

__global__ void k_deg_edges(const int* __restrict__ dst,
                            const float* __restrict__ ew, int E) {
    int e = blockIdx.x * blockDim.x + threadIdx.x;
    if (e < E) atomicAdd(&g_dinv[dst[e]], ew[e]);
}

__global__ void k_dinv(int n) {
    int i = blockIdx.x * blockDim.x + threadIdx.x;
    if (i < n) {
        float v = g_dinv[i];
        g_dinv[i] = (v > 0.0f) ? rsqrtf(v) : 0.0f;
    }
}

// ---------------- per-edge norm: g_norm[e] = dinv[s]*w*dinv[d] ----------------
__global__ void k_norm(const int* __restrict__ srcI,
                       const int* __restrict__ dstI,
                       const float* __restrict__ ew, int E) {
    int e = blockIdx.x * blockDim.x + threadIdx.x;
    if (e < E)
        g_norm[e] = g_dinv[srcI[e]] * ew[e] * g_dinv[dstI[e]];
}

// ---------------- GEMM1: x[N,128] @ W1[128,64] -> g_B0 ----------------
__global__ void k_gemm1(const float* __restrict__ x,
                        const float* __restrict__ W, int n) {
    __shared__ float Ws[IN_DIM * HID];  // 32KB
    for (int i = threadIdx.x; i < IN_DIM * HID; i += blockDim.x)
        Ws[i] = W[i];
    __syncthreads();

    int row = blockIdx.x * 4 + (threadIdx.x >> 6);
    int col = threadIdx.x & 63;
    if (row >= n) return;
    const float* xr = x + (size_t)row * IN_DIM;
    float acc = 0.0f;
#pragma unroll 8
    for (int k = 0; k < IN_DIM; k++)
        acc = fmaf(__ldg(&xr[k]), Ws[k * HID + col], acc);
    g_B0[(size_t)row * HID + col] = acc;
}

// ---------------- GEMM2: g_B0[N,64] @ (Wmu|Wlv)[64,64] -> g_B1 ----------------
__global__ void k_gemm2(const float* __restrict__ Wmu,
                        const float* __restrict__ Wlv, int n) {
    __shared__ float Ws[HID * HID];  // 16KB
    for (int i = threadIdx.x; i < HID * HID; i += blockDim.x) {
        int k = i >> 6, c = i & 63;
        Ws[i] = (c < LAT) ? Wmu[k * LAT + c] : Wlv[k * LAT + (c - LAT)];
    }
    __syncthreads();

    int row = blockIdx.x * 4 + (threadIdx.x >> 6);
    int col = threadIdx.x & 63;
    if (row >= n) return;
    const float* hr = &g_B0[(size_t)row * HID];
    float acc = 0.0f;
#pragma unroll 8
    for (int k = 0; k < HID; k++)
        acc = fmaf(hr[k], Ws[k * HID + col], acc);
    g_B1[(size_t)row * HID + col] = acc;
}

// ---------------- self-loop init: ACC = dinv^2 * FEAT ----------------
// layer 0: feat=g_B0, acc=g_B1 ; layer 1: feat=g_B1, acc=g_B2
__global__ void k_selfinit(int layer, int n) {
    const float* feat = (layer == 0) ? g_B0 : g_B1;
    float*       acc  = (layer == 0) ? g_B1 : g_B2;
    int idx = blockIdx.x * blockDim.x + threadIdx.x;
    if (idx < n * HID) {
        int i = idx >> 6;
        float di = g_dinv[i];
        acc[idx] = di * di * feat[idx];
    }
}

// ---------------- edge scatter: ACC[dst] += norm * FEAT[src] ----------------
// 16 threads per edge, 4 cols each (float4 gather, 4 scalar atomics)
__global__ void k_scatter(const int* __restrict__ srcI,
                          const int* __restrict__ dstI,
                          int layer, int E) {
    const float* feat = (layer == 0) ? g_B0 : g_B1;
    float*       acc  = (layer == 0) ? g_B1 : g_B2;
    int t = blockIdx.x * blockDim.x + threadIdx.x;
    int e = t >> 4;
    if (e >= E) return;
    int cg = (t & 15) << 2;
    int s = srcI[e];
    int d = dstI[e];
    float nrm = g_norm[e];
    float4 v = *reinterpret_cast<const float4*>(&feat[(size_t)s * HID + cg]);
    float* ap = &acc[(size_t)d * HID + cg];
    atomicAdd(ap + 0, nrm * v.x);
    atomicAdd(ap + 1, nrm * v.y);
    atomicAdd(ap + 2, nrm * v.z);
    atomicAdd(ap + 3, nrm * v.w);
}

// ---------------- relu + bias: g_B0 = relu(g_B1 + b1) ----------------
__global__ void k_relu_bias(const float* __restrict__ b1, int n) {
    int idx = blockIdx.x * blockDim.x + threadIdx.x;
    if (idx < n * HID) {
        float v = g_B1[idx] + __ldg(&b1[idx & 63]);
        g_B0[idx] = v > 0.0f ? v : 0.0f;
    }
}

// ---------------- output: split mu|lv from g_B2, add biases ----------------
__global__ void k_out(const float* __restrict__ bmu,
                      const float* __restrict__ blv,
                      float* __restrict__ out, int n) {
    int idx = blockIdx.x * blockDim.x + threadIdx.x;
    if (idx < n * HID) {
        int i = idx >> 6, c = idx & 63;
        float v = g_B2[idx];
        if (c < LAT)
            out[(size_t)i * LAT + c] = v + __ldg(&bmu[c]);
        else
            out[(size_t)n * LAT + (size_t)i * LAT + (c - LAT)] = v + __ldg(&blv[c - LAT]);
    }
}

extern "C" void kernel_launch(void* const* d_in, const int* in_sizes, int n_in,
                              void* d_out, int out_size) {
    const float* x   = (const float*)d_in[0];
    const int*   ei  = (const int*)d_in[1];     // int32 (JAX x64 disabled)
    const float* ew  = (const float*)d_in[2];
    const float* W1  = (const float*)d_in[3];
    const float* b1  = (const float*)d_in[4];
    const float* Wmu = (const float*)d_in[5];
    const float* bmu = (const float*)d_in[6];
    const float* Wlv = (const float*)d_in[7];
    const float* blv = (const float*)d_in[8];
    float* out       = (float*)d_out;

    int n = in_sizes[0] / IN_DIM;   // 100000
    int E = in_sizes[2];            // 1600000
    const int* srcI = ei;
    const int* dstI = ei + E;

    const int T = 256;
    int gridNF = (int)(((long long)n * HID + T - 1) / T);
    int gridE  = (E + T - 1) / T;
    int gridSc = (int)(((long long)E * 16 + T - 1) / T);

    // 1) degree + dinv + per-edge norm
    k_init_deg<<<(n + T - 1) / T, T>>>(n);
    k_deg_edges<<<gridE, T>>>(dstI, ew, E);
    k_dinv<<<(n + T - 1) / T, T>>>(n);
    k_norm<<<gridE, T>>>(srcI, dstI, ew, E);

    // 2) layer 1: XW1 -> propagate -> relu+bias
    k_gemm1<<<(n + 3) / 4, T>>>(x, W1, n);
    k_selfinit<<<gridNF, T>>>(0, n);
    k_scatter<<<gridSc, T>>>(srcI, dstI, 0, E);
    k_relu_bias<<<gridNF, T>>>(b1, n);  // H in g_B0

    // 3) layer 2 fused mu|lv: H@Wcat -> propagate -> split+bias
    k_gemm2<<<(n + 3) / 4, T>>>(Wmu, Wlv, n);          // HW in g_B1
    k_selfinit<<<gridNF, T>>>(1, n);
    k_scatter<<<gridSc, T>>>(srcI, dstI, 1, E);
    k_out<<<gridNF, T>>>(bmu, blv, out, n);
}

// round 15
// speedup vs baseline: 1.3753x; 1.3753x over previous
#include <cuda_runtime.h>
#include <stdint.h>

#define MAXN 100000
#define MAXE 1600000
#define IN_DIM 128
#define HID 64
#define LAT 32

// Scratch: device globals, referenced ONLY from device code.
__device__ __align__(16) float g_dinv[MAXN];
__device__ __align__(16) float g_norm[MAXE];       // per-edge normalized weight
__device__ __align__(16) float g_B0[MAXN * HID];   // XW1 feat, later H
__device__ __align__(16) float g_B1[MAXN * HID];   // ACC1, later HWcat feat
__device__ __align__(16) float g_B2[MAXN * HID];   // ACC2 (fused mu|lv pre-bias)

__device__ __forceinline__ void red_add_v4(float* p, float a, float b, float c, float d) {
    asm volatile("red.global.add.v4.f32 [%0], {%1,%2,%3,%4};"
                 :: "l"(p), "f"(a), "f"(b), "f"(c), "f"(d) : "memory");
}

// ---------------- degree ----------------
__global__ void k_init_deg(int n) {
    int i = blockIdx.x * blockDim.x + threadIdx.x;
    if (i < n) g_dinv[i] = 1.0f;  // self-loop weight
}

__global__ void k_deg_edges(const int* __restrict__ dst,
                            const float* __restrict__ ew, int E) {
    int e = blockIdx.x * blockDim.x + threadIdx.x;
    if (e < E) atomicAdd(&g_dinv[dst[e]], ew[e]);
}

__global__ void k_dinv(int n) {
    int i = blockIdx.x * blockDim.x + threadIdx.x;
    if (i < n) {
        float v = g_dinv[i];
        g_dinv[i] = (v > 0.0f) ? rsqrtf(v) : 0.0f;
    }
}

// ---------------- per-edge norm ----------------
__global__ void k_norm(const int* __restrict__ srcI,
                       const int* __restrict__ dstI,
                       const float* __restrict__ ew, int E) {
    int e = blockIdx.x * blockDim.x + threadIdx.x;
    if (e < E)
        g_norm[e] = g_dinv[srcI[e]] * ew[e] * g_dinv[dstI[e]];
}

// ---------------- GEMM1 + fused self-loop init ----------------
// g_B0 = x@W1 ; g_B1 = dinv^2 * g_B0
__global__ void k_gemm1(const float* __restrict__ x,
                        const float* __restrict__ W, int n) {
    __shared__ float Ws[IN_DIM * HID];  // 32KB
    for (int i = threadIdx.x; i < IN_DIM * HID; i += blockDim.x)
        Ws[i] = W[i];
    __syncthreads();

    int row = blockIdx.x * 4 + (threadIdx.x >> 6);
    int col = threadIdx.x & 63;
    if (row >= n) return;
    const float* xr = x + (size_t)row * IN_DIM;
    float acc = 0.0f;
#pragma unroll 8
    for (int k = 0; k < IN_DIM; k++)
        acc = fmaf(__ldg(&xr[k]), Ws[k * HID + col], acc);
    size_t o = (size_t)row * HID + col;
    float di = g_dinv[row];
    g_B0[o] = acc;
    g_B1[o] = di * di * acc;
}

// ---------------- GEMM2 + fused self-loop init ----------------
// g_B1 = g_B0@(Wmu|Wlv) ; g_B2 = dinv^2 * g_B1
__global__ void k_gemm2(const float* __restrict__ Wmu,
                        const float* __restrict__ Wlv, int n) {
    __shared__ float Ws[HID * HID];  // 16KB
    for (int i = threadIdx.x; i < HID * HID; i += blockDim.x) {
        int k = i >> 6, c = i & 63;
        Ws[i] = (c < LAT) ? Wmu[k * LAT + c] : Wlv[k * LAT + (c - LAT)];
    }
    __syncthreads();

    int row = blockIdx.x * 4 + (threadIdx.x >> 6);
    int col = threadIdx.x & 63;
    if (row >= n) return;
    const float* hr = &g_B0[(size_t)row * HID];
    float acc = 0.0f;
#pragma unroll 8
    for (int k = 0; k < HID; k++)
        acc = fmaf(hr[k], Ws[k * HID + col], acc);
    size_t o = (size_t)row * HID + col;
    float di = g_dinv[row];
    g_B1[o] = acc;
    g_B2[o] = di * di * acc;
}

// ---------------- edge scatter: ACC[dst] += norm * FEAT[src] ----------------
// 16 threads per edge, 4 cols each: float4 gather + ONE red.global.add.v4.f32
__global__ void k_scatter(const int* __restrict__ srcI,
                          const int* __restrict__ dstI,
                          int layer, int E) {
    const float* feat = (layer == 0) ? g_B0 : g_B1;
    float*       acc  = (layer == 0) ? g_B1 : g_B2;
    int t = blockIdx.x * blockDim.x + threadIdx.x;
    int e = t >> 4;
    if (e >= E) return;
    int cg = (t & 15) << 2;
    int s = srcI[e];
    int d = dstI[e];
    float nrm = g_norm[e];
    float4 v = *reinterpret_cast<const float4*>(&feat[(size_t)s * HID + cg]);
    red_add_v4(&acc[(size_t)d * HID + cg],
               nrm * v.x, nrm * v.y, nrm * v.z, nrm * v.w);
}

// ---------------- relu + bias: g_B0 = relu(g_B1 + b1) ----------------
__global__ void k_relu_bias(const float* __restrict__ b1, int n) {
    int idx = blockIdx.x * blockDim.x + threadIdx.x;
    if (idx < n * HID) {
        float v = g_B1[idx] + __ldg(&b1[idx & 63]);
        g_B0[idx] = v > 0.0f ? v : 0.0f;
    }
}

// ---------------- output: split mu|lv from g_B2, add biases ----------------
__global__ void k_out(const float* __restrict__ bmu,
                      const float* __restrict__ blv,
                      float* __restrict__ out, int n) {
    int idx = blockIdx.x * blockDim.x + threadIdx.x;
    if (idx < n * HID) {
        int i = idx >> 6, c = idx & 63;
        float v = g_B2[idx];
        if (c < LAT)
            out[(size_t)i * LAT + c] = v + __ldg(&bmu[c]);
        else
            out[(size_t)n * LAT + (size_t)i * LAT + (c - LAT)] = v + __ldg(&blv[c - LAT]);
    }
}

extern "C" void kernel_launch(void* const* d_in, const int* in_sizes, int n_in,
                              void* d_out, int out_size) {
    const float* x   = (const float*)d_in[0];
    const int*   ei  = (const int*)d_in[1];     // int32 (JAX x64 disabled)
    const float* ew  = (const float*)d_in[2];
    const float* W1  = (const float*)d_in[3];
    const float* b1  = (const float*)d_in[4];
    const float* Wmu = (const float*)d_in[5];
    const float* bmu = (const float*)d_in[6];
    const float* Wlv = (const float*)d_in[7];
    const float* blv = (const float*)d_in[8];
    float* out       = (float*)d_out;

    int n = in_sizes[0] / IN_DIM;   // 100000
    int E = in_sizes[2];            // 1600000
    const int* srcI = ei;
    const int* dstI = ei + E;

    const int T = 256;
    int gridNF = (int)(((long long)n * HID + T - 1) / T);
    int gridE  = (E + T - 1) / T;
    int gridSc = (int)(((long long)E * 16 + T - 1) / T);

    // 1) degree + dinv + per-edge norm
    k_init_deg<<<(n + T - 1) / T, T>>>(n);
    k_deg_edges<<<gridE, T>>>(dstI, ew, E);
    k_dinv<<<(n + T - 1) / T, T>>>(n);
    k_norm<<<gridE, T>>>(srcI, dstI, ew, E);

    // 2) layer 1: XW1 (+selfinit) -> propagate -> relu+bias
    k_gemm1<<<(n + 3) / 4, T>>>(x, W1, n);
    k_scatter<<<gridSc, T>>>(srcI, dstI, 0, E);
    k_relu_bias<<<gridNF, T>>>(b1, n);  // H in g_B0

    // 3) layer 2 fused mu|lv: H@Wcat (+selfinit) -> propagate -> split+bias
    k_gemm2<<<(n + 3) / 4, T>>>(Wmu, Wlv, n);
    k_scatter<<<gridSc, T>>>(srcI, dstI, 1, E);
    k_out<<<gridNF, T>>>(bmu, blv, out, n);
}

// round 16
// speedup vs baseline: 1.6985x; 1.2350x over previous
#include <cuda_runtime.h>
#include <stdint.h>

#define MAXN 100000
#define MAXE 1600000
#define IN_DIM 128
#define HID 64
#define LAT 32
#define NB_SCAN ((MAXN + 255) / 256)   // 391 blocks

// Scratch (device globals only; reset every launch where needed)
__device__ __align__(16) float g_dinv[MAXN];
__device__ int   g_cnt[MAXN];            // in-degree histogram
__device__ int   g_cur[MAXN];            // build cursor
__device__ int   g_rowptr[MAXN + 1];
__device__ int   g_bsum[NB_SCAN];
__device__ int   g_boff[NB_SCAN];
__device__ __align__(16) int   g_csrc[MAXE];    // CSR src ids
__device__ __align__(16) float g_cnorm[MAXE];   // CSR edge norms
__device__ __align__(16) float g_B0[MAXN * HID]; // XW1
__device__ __align__(16) float g_B1[MAXN * HID]; // H
__device__ __align__(16) float g_B2[MAXN * HID]; // HWcat

// ---------------- init: dinv=1 (self loop), cnt=cur=0 ----------------
__global__ void k_init(int n) {
    int i = blockIdx.x * blockDim.x + threadIdx.x;
    if (i < n) { g_dinv[i] = 1.0f; g_cnt[i] = 0; g_cur[i] = 0; }
}

// ---------------- weighted degree + histogram ----------------
__global__ void k_deg_hist(const int* __restrict__ dst,
                           const float* __restrict__ ew, int E) {
    int e = blockIdx.x * blockDim.x + threadIdx.x;
    if (e < E) {
        int d = dst[e];
        atomicAdd(&g_dinv[d], ew[e]);
        atomicAdd(&g_cnt[d], 1);
    }
}

__global__ void k_dinv(int n) {
    int i = blockIdx.x * blockDim.x + threadIdx.x;
    if (i < n) {
        float v = g_dinv[i];
        g_dinv[i] = (v > 0.0f) ? rsqrtf(v) : 0.0f;
    }
}

// ---------------- exclusive scan of g_cnt -> g_rowptr (2-level) ----------------
__global__ void k_scan1(int n) {
    __shared__ int sh[256];
    int gid = blockIdx.x * 256 + threadIdx.x;
    int v = (gid < n) ? g_cnt[gid] : 0;
    sh[threadIdx.x] = v;
    __syncthreads();
    for (int off = 1; off < 256; off <<= 1) {
        int t = (threadIdx.x >= off) ? sh[threadIdx.x - off] : 0;
        __syncthreads();
        sh[threadIdx.x] += t;
        __syncthreads();
    }
    if (gid < n) g_rowptr[gid] = sh[threadIdx.x] - v;  // exclusive
    if (threadIdx.x == 255) g_bsum[blockIdx.x] = sh[255];
}

__global__ void k_scan2(int nb) {
    __shared__ int sh[512];
    int v = (threadIdx.x < nb) ? g_bsum[threadIdx.x] : 0;
    sh[threadIdx.x] = v;
    __syncthreads();
    for (int off = 1; off < 512; off <<= 1) {
        int t = (threadIdx.x >= off) ? sh[threadIdx.x - off] : 0;
        __syncthreads();
        sh[threadIdx.x] += t;
        __syncthreads();
    }
    if (threadIdx.x < nb) g_boff[threadIdx.x] = sh[threadIdx.x] - v;
}

__global__ void k_scan3(int n, int E) {
    int gid = blockIdx.x * 256 + threadIdx.x;
    if (gid < n) g_rowptr[gid] += g_boff[blockIdx.x];
    if (gid == 0) g_rowptr[n] = E;
}

// ---------------- CSR build: bucket-scatter src + norm ----------------
__global__ void k_build(const int* __restrict__ srcI,
                        const int* __restrict__ dstI,
                        const float* __restrict__ ew, int E) {
    int e = blockIdx.x * blockDim.x + threadIdx.x;
    if (e >= E) return;
    int s = srcI[e];
    int d = dstI[e];
    int pos = g_rowptr[d] + atomicAdd(&g_cur[d], 1);
    g_csrc[pos] = s;
    g_cnorm[pos] = g_dinv[s] * ew[e] * g_dinv[d];
}

// ---------------- GEMM1: x[N,128] @ W1[128,64] -> g_B0 ----------------
__global__ void k_gemm1(const float* __restrict__ x,
                        const float* __restrict__ W, int n) {
    __shared__ float Ws[IN_DIM * HID];  // 32KB
    for (int i = threadIdx.x; i < IN_DIM * HID; i += blockDim.x)
        Ws[i] = W[i];
    __syncthreads();

    int row = blockIdx.x * 4 + (threadIdx.x >> 6);
    int col = threadIdx.x & 63;
    if (row >= n) return;
    const float* xr = x + (size_t)row * IN_DIM;
    float acc = 0.0f;
#pragma unroll 8
    for (int k = 0; k < IN_DIM; k++)
        acc = fmaf(__ldg(&xr[k]), Ws[k * HID + col], acc);
    g_B0[(size_t)row * HID + col] = acc;
}

// ---------------- GEMM2: g_B1[N,64] @ (Wmu|Wlv)[64,64] -> g_B2 ----------------
__global__ void k_gemm2(const float* __restrict__ Wmu,
                        const float* __restrict__ Wlv, int n) {
    __shared__ float Ws[HID * HID];  // 16KB
    for (int i = threadIdx.x; i < HID * HID; i += blockDim.x) {
        int k = i >> 6, c = i & 63;
        Ws[i] = (c < LAT) ? Wmu[k * LAT + c] : Wlv[k * LAT + (c - LAT)];
    }
    __syncthreads();

    int row = blockIdx.x * 4 + (threadIdx.x >> 6);
    int col = threadIdx.x & 63;
    if (row >= n) return;
    const float* hr = &g_B1[(size_t)row * HID];
    float acc = 0.0f;
#pragma unroll 8
    for (int k = 0; k < HID; k++)
        acc = fmaf(hr[k], Ws[k * HID + col], acc);
    g_B2[(size_t)row * HID + col] = acc;
}

// ---------------- CSR propagate + fused epilogue ----------------
// 16 threads per dst node, 4 cols each. No atomics.
// layer 0: feat=g_B0, epilogue relu(acc+b1) -> g_B1
// layer 1: feat=g_B2, epilogue split mu|lv + bias -> out
__global__ void k_prop(const float* __restrict__ b0,   // b1 (layer0)
                       const float* __restrict__ bmu,  // layer1
                       const float* __restrict__ blv,  // layer1
                       float* __restrict__ out,        // layer1
                       int layer, int n) {
    int t = blockIdx.x * blockDim.x + threadIdx.x;
    int d = t >> 4;
    if (d >= n) return;
    int cg = (t & 15) << 2;

    const float* feat = (layer == 0) ? g_B0 : g_B2;

    float di = g_dinv[d];
    float4 f = *reinterpret_cast<const float4*>(&feat[(size_t)d * HID + cg]);
    float slw = di * di;
    float ax = slw * f.x, ay = slw * f.y, az = slw * f.z, aw = slw * f.w;

    int beg = g_rowptr[d];
    int end = g_rowptr[d + 1];
    int i = beg;
    // 2-way interleave for MLP
    for (; i + 1 < end; i += 2) {
        int s0 = g_csrc[i];     float n0 = g_cnorm[i];
        int s1 = g_csrc[i + 1]; float n1 = g_cnorm[i + 1];
        float4 v0 = *reinterpret_cast<const float4*>(&feat[(size_t)s0 * HID + cg]);
        float4 v1 = *reinterpret_cast<const float4*>(&feat[(size_t)s1 * HID + cg]);
        ax = fmaf(n0, v0.x, ax); ay = fmaf(n0, v0.y, ay);
        az = fmaf(n0, v0.z, az); aw = fmaf(n0, v0.w, aw);
        ax = fmaf(n1, v1.x, ax); ay = fmaf(n1, v1.y, ay);
        az = fmaf(n1, v1.z, az); aw = fmaf(n1, v1.w, aw);
    }
    if (i < end) {
        int s0 = g_csrc[i]; float n0 = g_cnorm[i];
        float4 v0 = *reinterpret_cast<const float4*>(&feat[(size_t)s0 * HID + cg]);
        ax = fmaf(n0, v0.x, ax); ay = fmaf(n0, v0.y, ay);
        az = fmaf(n0, v0.z, az); aw = fmaf(n0, v0.w, aw);
    }

    if (layer == 0) {
        ax += __ldg(&b0[cg + 0]); ay += __ldg(&b0[cg + 1]);
        az += __ldg(&b0[cg + 2]); aw += __ldg(&b0[cg + 3]);
        float4 r;
        r.x = ax > 0.0f ? ax : 0.0f;
        r.y = ay > 0.0f ? ay : 0.0f;
        r.z = az > 0.0f ? az : 0.0f;
        r.w = aw > 0.0f ? aw : 0.0f;
        *reinterpret_cast<float4*>(&g_B1[(size_t)d * HID + cg]) = r;
    } else {
        float4 r;
        if (cg < LAT) {
            r.x = ax + __ldg(&bmu[cg + 0]); r.y = ay + __ldg(&bmu[cg + 1]);
            r.z = az + __ldg(&bmu[cg + 2]); r.w = aw + __ldg(&bmu[cg + 3]);
            *reinterpret_cast<float4*>(&out[(size_t)d * LAT + cg]) = r;
        } else {
            int c = cg - LAT;
            r.x = ax + __ldg(&blv[c + 0]); r.y = ay + __ldg(&blv[c + 1]);
            r.z = az + __ldg(&blv[c + 2]); r.w = aw + __ldg(&blv[c + 3]);
            *reinterpret_cast<float4*>(&out[(size_t)n * LAT + (size_t)d * LAT + c]) = r;
        }
    }
}

extern "C" void kernel_launch(void* const* d_in, const int* in_sizes, int n_in,
                              void* d_out, int out_size) {
    const float* x   = (const float*)d_in[0];
    const int*   ei  = (const int*)d_in[1];     // int32
    const float* ew  = (const float*)d_in[2];
    const float* W1  = (const float*)d_in[3];
    const float* b1  = (const float*)d_in[4];
    const float* Wmu = (const float*)d_in[5];
    const float* bmu = (const float*)d_in[6];
    const float* Wlv = (const float*)d_in[7];
    const float* blv = (const float*)d_in[8];
    float* out       = (float*)d_out;

    int n = in_sizes[0] / IN_DIM;   // 100000
    int E = in_sizes[2];            // 1600000
    const int* srcI = ei;
    const int* dstI = ei + E;

    const int T = 256;
    int gridN  = (n + T - 1) / T;
    int gridE  = (E + T - 1) / T;
    int gridP  = (int)(((long long)n * 16 + T - 1) / T);
    int nbScan = (n + 255) / 256;

    // 1) degree + histogram + dinv
    k_init<<<gridN, T>>>(n);
    k_deg_hist<<<gridE, T>>>(dstI, ew, E);
    k_dinv<<<gridN, T>>>(n);

    // 2) CSR build
    k_scan1<<<nbScan, 256>>>(n);
    k_scan2<<<1, 512>>>(nbScan);
    k_scan3<<<nbScan, 256>>>(n, E);
    k_build<<<gridE, T>>>(srcI, dstI, ew, E);

    // 3) layer 1: XW1 -> CSR propagate (+relu+b1) -> g_B1
    k_gemm1<<<(n + 3) / 4, T>>>(x, W1, n);
    k_prop<<<gridP, T>>>(b1, bmu, blv, out, 0, n);

    // 4) layer 2: H@(Wmu|Wlv) -> CSR propagate (+split+bias) -> out
    k_gemm2<<<(n + 3) / 4, T>>>(Wmu, Wlv, n);
    k_prop<<<gridP, T>>>(b1, bmu, blv, out, 1, n);
}